// round 6
// baseline (speedup 1.0000x reference)
#include <cuda_runtime.h>
#include <cuda_bf16.h>
#include <math.h>
#include <stdint.h>

#define NB 256
#define NT 36
#define NS 96
#define ND 1024
#define NH 1024
#define N3 3072

// ===================== device scratch =====================
__device__ __align__(16) __nv_bfloat16 g_th[9216*1024], g_tl[9216*1024];
__device__ __align__(16) __nv_bfloat16 g_aWh[96*2048],  g_aWl[96*2048];
__device__ __align__(16) __nv_bfloat16 g_cWh[1024*2048], g_cWl[1024*2048];
__device__ __align__(16) __nv_bfloat16 g_Wgh[2*2*3072*1024], g_Wgl[2*2*3072*1024];
__device__ __align__(16) __nv_bfloat16 g_o1h[1024*1024], g_o1l[1024*1024];
__device__ __align__(16) __nv_bfloat16 g_o2h[1024*1024], g_o2l[1024*1024];
__device__ __align__(16) __nv_bfloat16 g_tmph[9216*1024], g_tmpl[9216*1024];
__device__ __align__(16) __nv_bfloat16 g_h1h[9216*1024], g_h1l[9216*1024];
__device__ float g_combx[9216*1024];
__device__ float g_lx[9216*96];
__device__ float g_lpart[4*256*96];
__device__ __align__(16) __nv_bfloat16 g_weh[256*1024], g_wel[256*1024];
__device__ __align__(16) __nv_bfloat16 g_a0h[256*2048], g_a0l[256*2048];
__device__ __align__(16) __nv_bfloat16 g_a1h[256*2048], g_a1l[256*2048];
__device__ float g_g[4*256*3072];          // split-K / gi-gh partials (also aliased by comb partials)
__device__ float g_hf[2*256*1024];

// ===================== helpers =====================
__device__ __forceinline__ void cpa16(uint32_t dst, const __nv_bfloat16* src) {
    asm volatile("cp.async.cg.shared.global [%0], [%1], 16;"
                 :: "r"(dst), "l"(__cvta_generic_to_global(src)));
}
__device__ __forceinline__ void ldsm4(uint32_t &r0, uint32_t &r1, uint32_t &r2, uint32_t &r3,
                                      const __nv_bfloat16* p) {
    uint32_t a = (uint32_t)__cvta_generic_to_shared(p);
    asm volatile("ldmatrix.sync.aligned.m8n8.x4.shared.b16 {%0,%1,%2,%3},[%4];"
                 : "=r"(r0), "=r"(r1), "=r"(r2), "=r"(r3) : "r"(a));
}
__device__ __forceinline__ void mma16816(float* c, const uint32_t* a, const uint32_t* b) {
    asm volatile("mma.sync.aligned.m16n8k16.row.col.f32.bf16.bf16.f32 "
                 "{%0,%1,%2,%3},{%4,%5,%6,%7},{%8,%9},{%0,%1,%2,%3};"
                 : "+f"(c[0]), "+f"(c[1]), "+f"(c[2]), "+f"(c[3])
                 : "r"(a[0]), "r"(a[1]), "r"(a[2]), "r"(a[3]), "r"(b[0]), "r"(b[1]));
}

// ===================== big GEMM: 128x128 CTA, 4 warps of 64x64, split-bf16 3-pass =====================
// C[m,n] = sum_k A[m,k]*W[n,k]. z decomposes: zA=z/kparts (A/W pointer select), zK=z%kparts (K chunk).
struct GB {
    const __nv_bfloat16 *Ah, *Al; long lda, saz;
    const __nv_bfloat16 *Wh, *Wl; long ldw, swz;
    float* Cf; long scz; long ldc;
    __nv_bfloat16 *Chi, *Clo;
    const float* bias;
    int K; long kz; int kparts;
};

#define BIGSM 81920   // 2 stages * 4 matrices * 128 rows * 80B

__global__ void __launch_bounds__(128) gemm_big(GB p)
{
    extern __shared__ __align__(16) __nv_bfloat16 smp[];   // halves
    const uint32_t smB = (uint32_t)__cvta_generic_to_shared(smp);

    const int tid = threadIdx.x, lane = tid & 31, wid = tid >> 5;
    const int wm0 = (wid & 1) * 64, wn0 = (wid >> 1) * 64;
    const int m0 = blockIdx.y * 128, n0 = blockIdx.x * 128, z = blockIdx.z;
    const int zA = z / p.kparts, zK = z - zA * p.kparts;

    const __nv_bfloat16* gA0 = p.Ah + (long)zA * p.saz;
    const __nv_bfloat16* gA1 = p.Al + (long)zA * p.saz;
    const __nv_bfloat16* gW0 = p.Wh + (long)zA * p.swz;
    const __nv_bfloat16* gW1 = p.Wl + (long)zA * p.swz;
    const long kstart = (long)zK * p.kz;
    const int niter = p.K / 32;

    float c[4][8][4];
#pragma unroll
    for (int mi = 0; mi < 4; mi++)
#pragma unroll
        for (int ni = 0; ni < 8; ni++)
#pragma unroll
            for (int q = 0; q < 4; q++) c[mi][ni][q] = 0.0f;

    auto issue = [&](int s, long gk) {
        const uint32_t sb = smB + s * 40960;
#pragma unroll
        for (int i = 0; i < 4; i++) {                       // 4 chunks per matrix per thread
            const int idx = tid + i * 128;
            const int r = idx >> 2, c16 = idx & 3;
            const uint32_t d = sb + r * 80 + c16 * 16;
            cpa16(d,                 gA0 + (long)(m0 + r) * p.lda + gk + c16 * 8);
            cpa16(d + 10240,         gA1 + (long)(m0 + r) * p.lda + gk + c16 * 8);
            cpa16(d + 20480,         gW0 + (long)(n0 + r) * p.ldw + gk + c16 * 8);
            cpa16(d + 30720,         gW1 + (long)(n0 + r) * p.ldw + gk + c16 * 8);
        }
        asm volatile("cp.async.commit_group;");
    };

    const int aRow = lane & 15, aCol = (lane >> 4) * 8;
    const int bRow = ((lane >> 4) & 1) * 8 + (lane & 7), bKoff = ((lane >> 3) & 1) * 8;

    issue(0, kstart);
    for (int k = 0; k < niter; k++) {
        const int s = k & 1;
        if (k + 1 < niter) {
            issue(s ^ 1, kstart + (long)(k + 1) * 32);
            asm volatile("cp.async.wait_group 1;");
        } else {
            asm volatile("cp.async.wait_group 0;");
        }
        __syncthreads();
        const __nv_bfloat16* st = smp + s * 20480;
#pragma unroll
        for (int kk = 0; kk < 2; kk++) {
            uint32_t ah[4][4], al[4][4];
#pragma unroll
            for (int mi = 0; mi < 4; mi++) {
                const int ro = (wm0 + mi * 16 + aRow) * 40 + kk * 16 + aCol;
                ldsm4(ah[mi][0], ah[mi][1], ah[mi][2], ah[mi][3], st + ro);
                ldsm4(al[mi][0], al[mi][1], al[mi][2], al[mi][3], st + 5120 + ro);
            }
#pragma unroll
            for (int j2 = 0; j2 < 4; j2++) {
                const int ro = (wn0 + j2 * 16 + bRow) * 40 + kk * 16 + bKoff;
                uint32_t wh[2][2], wl[2][2], r0, r1, r2, r3;
                ldsm4(r0, r1, r2, r3, st + 10240 + ro);
                wh[0][0] = r0; wh[0][1] = r1; wh[1][0] = r2; wh[1][1] = r3;
                ldsm4(r0, r1, r2, r3, st + 15360 + ro);
                wl[0][0] = r0; wl[0][1] = r1; wl[1][0] = r2; wl[1][1] = r3;
#pragma unroll
                for (int mi = 0; mi < 4; mi++) {
                    mma16816(c[mi][2*j2],   ah[mi], wh[0]);
                    mma16816(c[mi][2*j2],   ah[mi], wl[0]);
                    mma16816(c[mi][2*j2],   al[mi], wh[0]);
                    mma16816(c[mi][2*j2+1], ah[mi], wh[1]);
                    mma16816(c[mi][2*j2+1], ah[mi], wl[1]);
                    mma16816(c[mi][2*j2+1], al[mi], wh[1]);
                }
            }
        }
        __syncthreads();
    }

    float* Cf = p.Cf ? p.Cf + (long)z * p.scz : nullptr;
#pragma unroll
    for (int mi = 0; mi < 4; mi++) {
#pragma unroll
        for (int ni = 0; ni < 8; ni++) {
            const int col = n0 + wn0 + ni * 8 + (lane & 3) * 2;
            float b0 = 0.f, b1 = 0.f;
            if (p.bias) { b0 = p.bias[col]; b1 = p.bias[col + 1]; }
#pragma unroll
            for (int h = 0; h < 2; h++) {
                const int r = m0 + wm0 + mi * 16 + (lane >> 2) + h * 8;
                float v0 = c[mi][ni][h * 2] + b0, v1 = c[mi][ni][h * 2 + 1] + b1;
                if (Cf) *(float2*)&Cf[(long)r * p.ldc + col] = make_float2(v0, v1);
                if (p.Chi) {
                    __nv_bfloat16 h0 = __float2bfloat16(v0), h1 = __float2bfloat16(v1);
                    __nv_bfloat162 hh; hh.x = h0; hh.y = h1;
                    *(__nv_bfloat162*)&p.Chi[(long)r * p.ldc + col] = hh;
                    __nv_bfloat162 ll;
                    ll.x = __float2bfloat16(v0 - __bfloat162float(h0));
                    ll.y = __float2bfloat16(v1 - __bfloat162float(h1));
                    *(__nv_bfloat162*)&p.Clo[(long)r * p.ldc + col] = ll;
                }
            }
        }
    }
}

// ===================== small GEMM (logits, N=96) — R4 proven =====================
struct GP {
    const __nv_bfloat16 *Ah, *Al; long lda, saz;
    const __nv_bfloat16 *Wh, *Wl; long ldw, swz;
    float* Cf; long scz;
    long ldc;
    const float* bias;
    int K; long kz;
};

template<int BM, int BN, int WM, int WN>
__global__ void __launch_bounds__((BM/WM)*(BN/WN)*32)
gemm_bf16(GP p)
{
    constexpr int BK = 32, LDSH = BK + 8;
    constexpr int WPM = BM/WM, WPN = BN/WN, T = WPM*WPN*32;
    constexpr int MI = WM/16, NI = WN/8;
    __shared__ __align__(16) __nv_bfloat16 sm[2][2][(BM+BN)*LDSH];

    const int tid = threadIdx.x, lane = tid & 31, wid = tid >> 5;
    const int wm0 = (wid % WPM) * WM, wn0 = (wid / WPM) * WN;
    const int m0 = blockIdx.y * BM, n0 = blockIdx.x * BN, z = blockIdx.z;

    const __nv_bfloat16 *Ah = p.Ah + (long)z * p.saz, *Al = p.Al + (long)z * p.saz;
    const __nv_bfloat16 *Wh = p.Wh + (long)z * p.swz, *Wl = p.Wl + (long)z * p.swz;
    const long kstart = (long)z * p.kz;
    const int niter = p.K / BK;

    const uint32_t smbase = (uint32_t)__cvta_generic_to_shared(&sm[0][0][0]);
    constexpr uint32_t LST = (BM+BN)*LDSH*2;
    constexpr uint32_t SST = 2*LST;
    constexpr uint32_t BOFF = BM*LDSH*2;

    float c[MI][NI][4];
#pragma unroll
    for (int mi = 0; mi < MI; mi++)
#pragma unroll
        for (int ni = 0; ni < NI; ni++)
#pragma unroll
            for (int q = 0; q < 4; q++) c[mi][ni][q] = 0.0f;

    auto issue = [&](int s, long gk) {
        const uint32_t sb = smbase + s*SST;
#pragma unroll
        for (int i = 0; i < BM*4/T; i++) {
            int idx = tid + i*T; int r = idx >> 2; int c16 = idx & 3;
            long go = (long)(m0 + r) * p.lda + gk + c16*8;
            uint32_t d = sb + r*(LDSH*2) + c16*16;
            cpa16(d, Ah + go);
            cpa16(d + LST, Al + go);
        }
#pragma unroll
        for (int i = 0; i < BN*4/T; i++) {
            int idx = tid + i*T; int r = idx >> 2; int c16 = idx & 3;
            long go = (long)(n0 + r) * p.ldw + gk + c16*8;
            uint32_t d = sb + BOFF + r*(LDSH*2) + c16*16;
            cpa16(d, Wh + go);
            cpa16(d + LST, Wl + go);
        }
        asm volatile("cp.async.commit_group;");
    };

    const int aRow = lane & 15, aCol = (lane >> 4) * 8;
    const int bRow = ((lane >> 4) & 1) * 8 + (lane & 7), bKoff = ((lane >> 3) & 1) * 8;

    issue(0, kstart);
    for (int k = 0; k < niter; k++) {
        const int s = k & 1;
        if (k + 1 < niter) {
            issue(s ^ 1, kstart + (long)(k+1)*BK);
            asm volatile("cp.async.wait_group 1;");
        } else {
            asm volatile("cp.async.wait_group 0;");
        }
        __syncthreads();
#pragma unroll
        for (int kk = 0; kk < 2; kk++) {
            uint32_t ah[MI][4], al[MI][4];
#pragma unroll
            for (int mi = 0; mi < MI; mi++) {
                const int ro = (wm0 + mi*16 + aRow)*LDSH + kk*16 + aCol;
                ldsm4(ah[mi][0], ah[mi][1], ah[mi][2], ah[mi][3], &sm[s][0][ro]);
                ldsm4(al[mi][0], al[mi][1], al[mi][2], al[mi][3], &sm[s][1][ro]);
            }
            uint32_t wh[NI][2], wl[NI][2];
#pragma unroll
            for (int j2 = 0; j2 < NI/2; j2++) {
                const int ro = BM*LDSH + (wn0 + j2*16 + bRow)*LDSH + kk*16 + bKoff;
                uint32_t r0, r1, r2, r3;
                ldsm4(r0, r1, r2, r3, &sm[s][0][ro]);
                wh[2*j2][0] = r0; wh[2*j2][1] = r1; wh[2*j2+1][0] = r2; wh[2*j2+1][1] = r3;
                ldsm4(r0, r1, r2, r3, &sm[s][1][ro]);
                wl[2*j2][0] = r0; wl[2*j2][1] = r1; wl[2*j2+1][0] = r2; wl[2*j2+1][1] = r3;
            }
#pragma unroll
            for (int mi = 0; mi < MI; mi++)
#pragma unroll
                for (int ni = 0; ni < NI; ni++) {
                    mma16816(c[mi][ni], ah[mi], wh[ni]);
                    mma16816(c[mi][ni], ah[mi], wl[ni]);
                    mma16816(c[mi][ni], al[mi], wh[ni]);
                }
        }
        __syncthreads();
    }

    float* Cf = p.Cf + (long)z * p.scz;
#pragma unroll
    for (int mi = 0; mi < MI; mi++) {
#pragma unroll
        for (int ni = 0; ni < NI; ni++) {
            const int col = n0 + wn0 + ni*8 + (lane & 3)*2;
            float b0 = 0.f, b1 = 0.f;
            if (p.bias) { b0 = p.bias[col]; b1 = p.bias[col+1]; }
#pragma unroll
            for (int h = 0; h < 2; h++) {
                const int r = m0 + wm0 + mi*16 + (lane >> 2) + h*8;
                float v0 = c[mi][ni][h*2] + b0, v1 = c[mi][ni][h*2+1] + b1;
                *(float2*)&Cf[(long)r * p.ldc + col] = make_float2(v0, v1);
            }
        }
    }
}

// ===================== small kernels =====================
struct Segs {
    const float4* s[9];
    uint2 *h[9], *l[9];
    long off[10];
};

__global__ void k_splitall(Segs sg)
{
    long i = (long)blockIdx.x * 256 + threadIdx.x;
    if (i >= sg.off[9]) return;
    int seg = 0;
    while (i >= sg.off[seg + 1]) seg++;
    const long j = i - sg.off[seg];
    const float4 v = sg.s[seg][j];
    const float vv[4] = {v.x, v.y, v.z, v.w};
    __nv_bfloat16 h[4], l[4];
#pragma unroll
    for (int q = 0; q < 4; q++) {
        h[q] = __float2bfloat16(vv[q]);
        l[q] = __float2bfloat16(vv[q] - __bfloat162float(h[q]));
    }
    sg.h[seg][j] = *(uint2*)h;
    sg.l[seg][j] = *(uint2*)l;
}

__global__ void k_inith(const float* hidden)
{
    long idx = (long)blockIdx.x * 256 + threadIdx.x;
    float v = hidden[idx];
    g_hf[idx] = v;
    int l = (int)(idx >> 18); long rem = idx & 262143;
    int b = (int)(rem >> 10), j = (int)(rem & 1023);
    __nv_bfloat16 h = __float2bfloat16(v);
    __nv_bfloat16 lo = __float2bfloat16(v - __bfloat162float(h));
    __nv_bfloat16* dh = l ? g_a1h : g_a0h;
    __nv_bfloat16* dl = l ? g_a1l : g_a0l;
    dh[b*2048 + 1024 + j] = h; dl[b*2048 + 1024 + j] = lo;
}

__global__ void k_attn(const float* __restrict__ enc, float* __restrict__ out_attn, int t)
{
    const int b = blockIdx.x, tid = threadIdx.x;
    __shared__ float aw[NS];
    if (tid < 32) {
        const int lane = tid;
        float v[3];
#pragma unroll
        for (int u = 0; u < 3; u++) {
            const int s = u*32 + lane;
            float x = g_lx[((long)b*NT + t)*NS + s];
#pragma unroll
            for (int p = 0; p < 4; p++) x += g_lpart[p*24576 + b*NS + s];
            v[u] = x;
        }
        float mx = fmaxf(v[0], fmaxf(v[1], v[2]));
#pragma unroll
        for (int o = 16; o > 0; o >>= 1) mx = fmaxf(mx, __shfl_xor_sync(0xffffffffu, mx, o));
        float e[3], sum = 0.f;
#pragma unroll
        for (int u = 0; u < 3; u++) { e[u] = expf(v[u] - mx); sum += e[u]; }
#pragma unroll
        for (int o = 16; o > 0; o >>= 1) sum += __shfl_xor_sync(0xffffffffu, sum, o);
        const float inv = 1.0f / sum;
#pragma unroll
        for (int u = 0; u < 3; u++) {
            const int s = u*32 + lane;
            const float w = e[u] * inv;
            aw[s] = w;
            out_attn[((long)b*NT + t)*NS + s] = w;
        }
    }
    __syncthreads();
    float4 acc = make_float4(0.f, 0.f, 0.f, 0.f);
    const float4* row = reinterpret_cast<const float4*>(enc + (long)b*NS*NH) + tid;
#pragma unroll 4
    for (int s = 0; s < NS; s++) {
        const float4 q = row[(long)s * (NH/4)];
        const float w = aw[s];
        acc.x += w*q.x; acc.y += w*q.y; acc.z += w*q.z; acc.w += w*q.w;
    }
    const int base = b*1024 + tid*4;
    float vv[4] = {acc.x, acc.y, acc.z, acc.w};
    __nv_bfloat16 h[4], l[4];
#pragma unroll
    for (int i = 0; i < 4; i++) {
        h[i] = __float2bfloat16(vv[i]);
        l[i] = __float2bfloat16(vv[i] - __bfloat162float(h[i]));
    }
    *(uint2*)&g_weh[base] = *(uint2*)h;
    *(uint2*)&g_wel[base] = *(uint2*)l;
}

// reduce 4 comb split-K partials + combx (has bias), relu, split-bf16 -> a0[:,0:1024]
__global__ void k_combred(const float* __restrict__ addsrc)
{
    const int idx = blockIdx.x * 256 + threadIdx.x;  // 0..262143
    const int b = idx >> 10, j = idx & 1023;
    float v = g_g[idx] + g_g[262144 + idx] + g_g[2*262144 + idx] + g_g[3*262144 + idx]
            + addsrc[(long)b * 36864 + j];
    v = fmaxf(v, 0.0f);
    __nv_bfloat16 h = __float2bfloat16(v);
    g_a0h[b*2048 + j] = h;
    g_a0l[b*2048 + j] = __float2bfloat16(v - __bfloat162float(h));
}

// GRU gate: sums 2 split-K partials for gi (z=0,1) and gh (z=2,3)
__global__ void k_gate(const float* __restrict__ bi, const float* __restrict__ bh,
                       float* __restrict__ hf,
                       __nv_bfloat16* d1h, __nv_bfloat16* d1l,
                       __nv_bfloat16* d2h, __nv_bfloat16* d2l,
                       __nv_bfloat16* d3h, __nv_bfloat16* d3l, long d3off)
{
    const int idx = blockIdx.x * 256 + threadIdx.x;
    const int b = idx >> 10, j = idx & 1023;
    const long o0 = (long)b * N3;
    const float* g0 = g_g + o0;
    const float* g1 = g_g + 786432 + o0;
    const float* g2 = g_g + 2*786432 + o0;
    const float* g3 = g_g + 3*786432 + o0;
    const float ir = g0[j]      + g1[j]      + bi[j];
    const float hr = g2[j]      + g3[j]      + bh[j];
    const float iz = g0[j+1024] + g1[j+1024] + bi[j+1024];
    const float hz = g2[j+1024] + g3[j+1024] + bh[j+1024];
    const float in_ = g0[j+2048] + g1[j+2048] + bi[j+2048];
    const float hn = g2[j+2048] + g3[j+2048] + bh[j+2048];
    const float r = 1.0f / (1.0f + expf(-(ir + hr)));
    const float z = 1.0f / (1.0f + expf(-(iz + hz)));
    const float n = tanhf(in_ + r * hn);
    const float h = (1.0f - z) * n + z * hf[idx];
    hf[idx] = h;
    __nv_bfloat16 hh = __float2bfloat16(h);
    __nv_bfloat16 hl = __float2bfloat16(h - __bfloat162float(hh));
    const long o = (long)b*2048 + j;
    d1h[o] = hh; d1l[o] = hl;
    if (d2h) { d2h[o] = hh; d2l[o] = hl; }
    if (d3h) { const long o3 = (long)b*36864 + d3off + j; d3h[o3] = hh; d3l[o3] = hl; }
}

__global__ void k_copy(float* __restrict__ dst, const float* __restrict__ src)
{
    const long i = (long)blockIdx.x * 256 + threadIdx.x;
    dst[i] = src[i];
}

// ===================== launch =====================
extern "C" void kernel_launch(void* const* d_in, const int* in_sizes, int n_in,
                              void* d_out, int out_size)
{
    const float* target = (const float*)d_in[0];
    const float* hidden = (const float*)d_in[1];
    const float* enc    = (const float*)d_in[2];
    const float* aW     = (const float*)d_in[3];
    const float* ab     = (const float*)d_in[4];
    const float* cW     = (const float*)d_in[5];
    const float* cb     = (const float*)d_in[6];
    const float* Wih    = (const float*)d_in[7];
    const float* Whh    = (const float*)d_in[8];
    const float* bih    = (const float*)d_in[9];
    const float* bhh    = (const float*)d_in[10];
    const float* o1W    = (const float*)d_in[11];
    const float* o1b    = (const float*)d_in[12];
    const float* o2W    = (const float*)d_in[13];
    const float* o2b    = (const float*)d_in[14];

    float* out_y    = (float*)d_out;
    float* out_h    = out_y + (long)NB*NT*ND;
    float* out_attn = out_h + (long)2*NB*NH;

    cudaFuncSetAttribute(gemm_big, cudaFuncAttributeMaxDynamicSharedMemorySize, BIGSM);

    __nv_bfloat16 *th, *tl, *aWh, *aWl, *cWh, *cWl, *Wgh, *Wgl, *o1h, *o1l, *o2h, *o2l;
    __nv_bfloat16 *tmph, *tmpl, *h1h, *h1l, *weh, *wel, *a0h, *a0l, *a1h, *a1l;
    float *combx, *lx, *lpart, *gg, *hf;
    cudaGetSymbolAddress((void**)&th, g_th);     cudaGetSymbolAddress((void**)&tl, g_tl);
    cudaGetSymbolAddress((void**)&aWh, g_aWh);   cudaGetSymbolAddress((void**)&aWl, g_aWl);
    cudaGetSymbolAddress((void**)&cWh, g_cWh);   cudaGetSymbolAddress((void**)&cWl, g_cWl);
    cudaGetSymbolAddress((void**)&Wgh, g_Wgh);   cudaGetSymbolAddress((void**)&Wgl, g_Wgl);
    cudaGetSymbolAddress((void**)&o1h, g_o1h);   cudaGetSymbolAddress((void**)&o1l, g_o1l);
    cudaGetSymbolAddress((void**)&o2h, g_o2h);   cudaGetSymbolAddress((void**)&o2l, g_o2l);
    cudaGetSymbolAddress((void**)&tmph, g_tmph); cudaGetSymbolAddress((void**)&tmpl, g_tmpl);
    cudaGetSymbolAddress((void**)&h1h, g_h1h);   cudaGetSymbolAddress((void**)&h1l, g_h1l);
    cudaGetSymbolAddress((void**)&weh, g_weh);   cudaGetSymbolAddress((void**)&wel, g_wel);
    cudaGetSymbolAddress((void**)&a0h, g_a0h);   cudaGetSymbolAddress((void**)&a0l, g_a0l);
    cudaGetSymbolAddress((void**)&a1h, g_a1h);   cudaGetSymbolAddress((void**)&a1l, g_a1l);
    cudaGetSymbolAddress((void**)&combx, g_combx);
    cudaGetSymbolAddress((void**)&lx, g_lx);
    cudaGetSymbolAddress((void**)&lpart, g_lpart);
    cudaGetSymbolAddress((void**)&gg, g_g);
    cudaGetSymbolAddress((void**)&hf, g_hf);

    // ---- 1: merged split conversions ----
    {
        Segs sg;
        const float* srcs[9] = {target, aW, cW, Wih, Whh, Wih + 3145728, Whh + 3145728, o1W, o2W};
        __nv_bfloat16* dh[9] = {th, aWh, cWh, Wgh, Wgh + 3145728, Wgh + 2L*3145728, Wgh + 3L*3145728, o1h, o2h};
        __nv_bfloat16* dl[9] = {tl, aWl, cWl, Wgl, Wgl + 3145728, Wgl + 2L*3145728, Wgl + 3L*3145728, o1l, o2l};
        const long cnt[9] = {2359296, 49152, 524288, 786432, 786432, 786432, 786432, 262144, 262144};
        long acc = 0;
        for (int i = 0; i < 9; i++) {
            sg.s[i] = (const float4*)srcs[i];
            sg.h[i] = (uint2*)dh[i];
            sg.l[i] = (uint2*)dl[i];
            sg.off[i] = acc; acc += cnt[i];
        }
        sg.off[9] = acc;
        k_splitall<<<(unsigned)((acc + 255) / 256), 256>>>(sg);
    }
    // ---- 2 ----
    k_inith<<<2048, 256>>>(hidden);
    // ---- 3: logits_x ----
    {
        GP p = {}; p.Ah = th; p.Al = tl; p.lda = 1024; p.Wh = aWh; p.Wl = aWl; p.ldw = 2048;
        p.Cf = lx; p.ldc = 96; p.bias = ab; p.K = 1024;
        gemm_bf16<64,32,32,16><<<dim3(3,144,1), 128>>>(p);
    }

    // ---- recurrent loop (combx launched inside t==0 so ncu -s5 captures it) ----
    for (int t = 0; t < NT; t++) {
        {   // logits_h (split-K=4)
            GP p = {}; p.Ah = a1h + 1024; p.Al = a1l + 1024; p.lda = 2048;
            p.Wh = aWh + 1024; p.Wl = aWl + 1024; p.ldw = 2048;
            p.Cf = lpart; p.scz = 24576; p.ldc = 96; p.K = 256; p.kz = 256;
            gemm_bf16<64,32,32,16><<<dim3(3,4,4), 128>>>(p);
        }
        k_attn<<<256, 256>>>(enc, out_attn, t);

        if (t == 0) {   // combx = target @ cW[:, :D].T + cb  (launch #6 -> ncu capture)
            GB q = {}; q.Ah = th; q.Al = tl; q.lda = 1024;
            q.Wh = cWh; q.Wl = cWl; q.ldw = 2048;
            q.Cf = combx; q.ldc = 1024; q.scz = 0; q.bias = cb; q.K = 1024; q.kparts = 1;
            gemm_big<<<dim3(8,72,1), 128, BIGSM>>>(q);
        }

        {   // comb GEMM: wenc @ cW[:, D:].T, split-K=4 partials into g_g
            GB q = {}; q.Ah = weh; q.Al = wel; q.lda = 1024;
            q.Wh = cWh + 1024; q.Wl = cWl + 1024; q.ldw = 2048;
            q.Cf = gg; q.scz = 262144; q.ldc = 1024; q.K = 256; q.kz = 256; q.kparts = 4;
            gemm_big<<<dim3(8,2,4), 128, BIGSM>>>(q);
        }
        k_combred<<<1024, 256>>>(combx + (long)t * 1024);

        {   // GRU layer 0: z = {gi k0, gi k1, gh k0, gh k1}
            GB q = {}; q.Ah = a0h; q.Al = a0l; q.lda = 2048; q.saz = 1024;
            q.Wh = Wgh; q.Wl = Wgl; q.ldw = 1024; q.swz = 3145728;
            q.Cf = gg; q.scz = 786432; q.ldc = 3072; q.K = 512; q.kz = 512; q.kparts = 2;
            gemm_big<<<dim3(24,2,4), 128, BIGSM>>>(q);
        }
        k_gate<<<1024, 256>>>(bih, bhh, hf, a1h, a1l, a0h + 1024, a0l + 1024,
                              nullptr, nullptr, 0);
        {   // GRU layer 1
            GB q = {}; q.Ah = a1h; q.Al = a1l; q.lda = 2048; q.saz = 1024;
            q.Wh = Wgh + 2L*3145728; q.Wl = Wgl + 2L*3145728; q.ldw = 1024; q.swz = 3145728;
            q.Cf = gg; q.scz = 786432; q.ldc = 3072; q.K = 512; q.kz = 512; q.kparts = 2;
            gemm_big<<<dim3(24,2,4), 128, BIGSM>>>(q);
        }
        k_gate<<<1024, 256>>>(bih + 3072, bhh + 3072, hf + 262144, a1h + 1024, a1l + 1024,
                              nullptr, nullptr, h1h, h1l, (long)t*1024);
    }

    // ---- deferred output head ----
    {
        GB q = {}; q.Ah = h1h; q.Al = h1l; q.lda = 1024;
        q.Wh = o1h; q.Wl = o1l; q.ldw = 1024;
        q.Chi = tmph; q.Clo = tmpl; q.ldc = 1024; q.bias = o1b; q.K = 1024; q.kparts = 1;
        gemm_big<<<dim3(8,72,1), 128, BIGSM>>>(q);
    }
    {
        GB q = {}; q.Ah = tmph; q.Al = tmpl; q.lda = 1024;
        q.Wh = o2h; q.Wl = o2l; q.ldw = 1024;
        q.Cf = out_y; q.ldc = 1024; q.bias = o2b; q.K = 1024; q.kparts = 1;
        gemm_big<<<dim3(8,72,1), 128, BIGSM>>>(q);
    }
    k_copy<<<2048, 256>>>(out_h, hf);
}

// round 7
// speedup vs baseline: 1.1615x; 1.1615x over previous
#include <cuda_runtime.h>
#include <cuda_bf16.h>
#include <math.h>
#include <stdint.h>

#define NB 256
#define NT 36
#define NS 96
#define ND 1024
#define NH 1024
#define N3 3072

// ===================== device scratch =====================
__device__ __align__(16) __nv_bfloat16 g_th[9216*1024], g_tl[9216*1024];
__device__ __align__(16) __nv_bfloat16 g_cWh[1024*2048], g_cWl[1024*2048];
__device__ __align__(16) __nv_bfloat16 g_aWh[96*2048],  g_aWl[96*2048];   // only x-half used
__device__ __align__(16) __nv_bfloat16 g_Wgh[2*2*3072*1024], g_Wgl[2*2*3072*1024]; // [l][ih/hh]
__device__ __align__(16) __nv_bfloat16 g_o1h[1024*1024], g_o1l[1024*1024];
__device__ __align__(16) __nv_bfloat16 g_o2h[1024*1024], g_o2l[1024*1024];
__device__ __align__(16) __nv_bfloat16 g_tmph[9216*1024], g_tmpl[9216*1024];
__device__ __align__(16) __nv_bfloat16 g_h1h[9216*1024], g_h1l[9216*1024];
__device__ float g_combx[9216*1024];
__device__ float g_lx[9216*96];
__device__ __align__(16) __nv_bfloat16 g_weh[256*1024], g_wel[256*1024];
__device__ __align__(16) __nv_bfloat16 g_ah[2*256*2048], g_al[2*256*2048]; // [l][b][ in(0:1024) | h(1024:2048) ]
__device__ float g_g[4*256*3072];   // slots: 0,1 = gi splitK partials; 2 = gh0; 3 = gh1 (comb reuses 0,1 region)
__device__ float g_hf[2*256*1024];

// ===================== helpers =====================
__device__ __forceinline__ void cpa16(uint32_t dst, const __nv_bfloat16* src) {
    asm volatile("cp.async.cg.shared.global [%0], [%1], 16;"
                 :: "r"(dst), "l"(__cvta_generic_to_global(src)));
}
__device__ __forceinline__ void ldsm4(uint32_t &r0, uint32_t &r1, uint32_t &r2, uint32_t &r3,
                                      const __nv_bfloat16* p) {
    uint32_t a = (uint32_t)__cvta_generic_to_shared(p);
    asm volatile("ldmatrix.sync.aligned.m8n8.x4.shared.b16 {%0,%1,%2,%3},[%4];"
                 : "=r"(r0), "=r"(r1), "=r"(r2), "=r"(r3) : "r"(a));
}
__device__ __forceinline__ void mma16816(float* c, const uint32_t* a, const uint32_t* b) {
    asm volatile("mma.sync.aligned.m16n8k16.row.col.f32.bf16.bf16.f32 "
                 "{%0,%1,%2,%3},{%4,%5,%6,%7},{%8,%9},{%0,%1,%2,%3};"
                 : "+f"(c[0]), "+f"(c[1]), "+f"(c[2]), "+f"(c[3])
                 : "r"(a[0]), "r"(a[1]), "r"(a[2]), "r"(a[3]), "r"(b[0]), "r"(b[1]));
}

// ===================== gemm_bf16: BMxBN CTA, split-bf16 3-pass interleaved, db-buffered =====================
struct GP {
    const __nv_bfloat16 *Ah, *Al; long lda, saz;
    const __nv_bfloat16 *Wh, *Wl; long ldw, swz;
    float* Cf; long scz; long ldc;
    const float* bias;
    int K; long kz;
};

template<int BM, int BN, int WM, int WN>
__global__ void __launch_bounds__((BM/WM)*(BN/WN)*32)
gemm_bf16(GP p)
{
    constexpr int BK = 32, LDSH = BK + 8;
    constexpr int WPM = BM/WM, WPN = BN/WN, T = WPM*WPN*32;
    constexpr int MI = WM/16, NI = WN/8;
    __shared__ __align__(16) __nv_bfloat16 sm[2][2][(BM+BN)*LDSH];

    const int tid = threadIdx.x, lane = tid & 31, wid = tid >> 5;
    const int wm0 = (wid % WPM) * WM, wn0 = (wid / WPM) * WN;
    const int m0 = blockIdx.y * BM, n0 = blockIdx.x * BN, z = blockIdx.z;

    const __nv_bfloat16 *Ah = p.Ah + (long)z * p.saz, *Al = p.Al + (long)z * p.saz;
    const __nv_bfloat16 *Wh = p.Wh + (long)z * p.swz, *Wl = p.Wl + (long)z * p.swz;
    const long kstart = (long)z * p.kz;
    const int niter = p.K / BK;

    const uint32_t smbase = (uint32_t)__cvta_generic_to_shared(&sm[0][0][0]);
    constexpr uint32_t LST = (BM+BN)*LDSH*2;
    constexpr uint32_t SST = 2*LST;
    constexpr uint32_t BOFF = BM*LDSH*2;

    float c[MI][NI][4];
#pragma unroll
    for (int mi = 0; mi < MI; mi++)
#pragma unroll
        for (int ni = 0; ni < NI; ni++)
#pragma unroll
            for (int q = 0; q < 4; q++) c[mi][ni][q] = 0.0f;

    auto issue = [&](int s, long gk) {
        const uint32_t sb = smbase + s*SST;
#pragma unroll
        for (int i = 0; i < BM*4/T; i++) {
            int idx = tid + i*T; int r = idx >> 2; int c16 = idx & 3;
            long go = (long)(m0 + r) * p.lda + gk + c16*8;
            uint32_t d = sb + r*(LDSH*2) + c16*16;
            cpa16(d, Ah + go);
            cpa16(d + LST, Al + go);
        }
#pragma unroll
        for (int i = 0; i < BN*4/T; i++) {
            int idx = tid + i*T; int r = idx >> 2; int c16 = idx & 3;
            long go = (long)(n0 + r) * p.ldw + gk + c16*8;
            uint32_t d = sb + BOFF + r*(LDSH*2) + c16*16;
            cpa16(d, Wh + go);
            cpa16(d + LST, Wl + go);
        }
        asm volatile("cp.async.commit_group;");
    };

    const int aRow = lane & 15, aCol = (lane >> 4) * 8;
    const int bRow = ((lane >> 4) & 1) * 8 + (lane & 7), bKoff = ((lane >> 3) & 1) * 8;

    issue(0, kstart);
    for (int k = 0; k < niter; k++) {
        const int s = k & 1;
        if (k + 1 < niter) {
            issue(s ^ 1, kstart + (long)(k+1)*BK);
            asm volatile("cp.async.wait_group 1;");
        } else {
            asm volatile("cp.async.wait_group 0;");
        }
        __syncthreads();
#pragma unroll
        for (int kk = 0; kk < 2; kk++) {
            uint32_t ah[MI][4], al[MI][4];
#pragma unroll
            for (int mi = 0; mi < MI; mi++) {
                const int ro = (wm0 + mi*16 + aRow)*LDSH + kk*16 + aCol;
                ldsm4(ah[mi][0], ah[mi][1], ah[mi][2], ah[mi][3], &sm[s][0][ro]);
                ldsm4(al[mi][0], al[mi][1], al[mi][2], al[mi][3], &sm[s][1][ro]);
            }
            uint32_t wh[NI][2], wl[NI][2];
#pragma unroll
            for (int j2 = 0; j2 < NI/2; j2++) {
                const int ro = BM*LDSH + (wn0 + j2*16 + bRow)*LDSH + kk*16 + bKoff;
                uint32_t r0, r1, r2, r3;
                ldsm4(r0, r1, r2, r3, &sm[s][0][ro]);
                wh[2*j2][0] = r0; wh[2*j2][1] = r1; wh[2*j2+1][0] = r2; wh[2*j2+1][1] = r3;
                ldsm4(r0, r1, r2, r3, &sm[s][1][ro]);
                wl[2*j2][0] = r0; wl[2*j2][1] = r1; wl[2*j2+1][0] = r2; wl[2*j2+1][1] = r3;
            }
#pragma unroll
            for (int mi = 0; mi < MI; mi++)
#pragma unroll
                for (int ni = 0; ni < NI; ni++) {
                    mma16816(c[mi][ni], ah[mi], wh[ni]);
                    mma16816(c[mi][ni], ah[mi], wl[ni]);
                    mma16816(c[mi][ni], al[mi], wh[ni]);
                }
        }
        __syncthreads();
    }

    float* Cf = p.Cf + (long)z * p.scz;
#pragma unroll
    for (int mi = 0; mi < MI; mi++) {
#pragma unroll
        for (int ni = 0; ni < NI; ni++) {
            const int col = n0 + wn0 + ni*8 + (lane & 3)*2;
            float b0 = 0.f, b1 = 0.f;
            if (p.bias) { b0 = p.bias[col]; b1 = p.bias[col+1]; }
#pragma unroll
            for (int h = 0; h < 2; h++) {
                const int r = m0 + wm0 + mi*16 + (lane >> 2) + h*8;
                *(float2*)&Cf[(long)r * p.ldc + col] =
                    make_float2(c[mi][ni][h*2] + b0, c[mi][ni][h*2+1] + b1);
            }
        }
    }
}

// ===================== gemm_big (pre/post, 128x128) =====================
struct GB {
    const __nv_bfloat16 *Ah, *Al; long lda;
    const __nv_bfloat16 *Wh, *Wl; long ldw;
    float* Cf; long ldc;
    __nv_bfloat16 *Chi, *Clo;
    const float* bias;
    int K;
};

#define BIGSM 81920

__global__ void __launch_bounds__(128) gemm_big(GB p)
{
    extern __shared__ __align__(16) __nv_bfloat16 smp[];
    const uint32_t smB = (uint32_t)__cvta_generic_to_shared(smp);

    const int tid = threadIdx.x, lane = tid & 31, wid = tid >> 5;
    const int wm0 = (wid & 1) * 64, wn0 = (wid >> 1) * 64;
    const int m0 = blockIdx.y * 128, n0 = blockIdx.x * 128;
    const int niter = p.K / 32;

    float c[4][8][4];
#pragma unroll
    for (int mi = 0; mi < 4; mi++)
#pragma unroll
        for (int ni = 0; ni < 8; ni++)
#pragma unroll
            for (int q = 0; q < 4; q++) c[mi][ni][q] = 0.0f;

    auto issue = [&](int s, long gk) {
        const uint32_t sb = smB + s * 40960;
#pragma unroll
        for (int i = 0; i < 4; i++) {
            const int idx = tid + i * 128;
            const int r = idx >> 2, c16 = idx & 3;
            const uint32_t d = sb + r * 80 + c16 * 16;
            cpa16(d,         p.Ah + (long)(m0 + r) * p.lda + gk + c16 * 8);
            cpa16(d + 10240, p.Al + (long)(m0 + r) * p.lda + gk + c16 * 8);
            cpa16(d + 20480, p.Wh + (long)(n0 + r) * p.ldw + gk + c16 * 8);
            cpa16(d + 30720, p.Wl + (long)(n0 + r) * p.ldw + gk + c16 * 8);
        }
        asm volatile("cp.async.commit_group;");
    };

    const int aRow = lane & 15, aCol = (lane >> 4) * 8;
    const int bRow = ((lane >> 4) & 1) * 8 + (lane & 7), bKoff = ((lane >> 3) & 1) * 8;

    issue(0, 0);
    for (int k = 0; k < niter; k++) {
        const int s = k & 1;
        if (k + 1 < niter) {
            issue(s ^ 1, (long)(k + 1) * 32);
            asm volatile("cp.async.wait_group 1;");
        } else {
            asm volatile("cp.async.wait_group 0;");
        }
        __syncthreads();
        const __nv_bfloat16* st = smp + s * 20480;
#pragma unroll
        for (int kk = 0; kk < 2; kk++) {
            uint32_t ah[4][4], al[4][4];
#pragma unroll
            for (int mi = 0; mi < 4; mi++) {
                const int ro = (wm0 + mi * 16 + aRow) * 40 + kk * 16 + aCol;
                ldsm4(ah[mi][0], ah[mi][1], ah[mi][2], ah[mi][3], st + ro);
                ldsm4(al[mi][0], al[mi][1], al[mi][2], al[mi][3], st + 5120 + ro);
            }
#pragma unroll
            for (int j2 = 0; j2 < 4; j2++) {
                const int ro = (wn0 + j2 * 16 + bRow) * 40 + kk * 16 + bKoff;
                uint32_t wh[2][2], wl[2][2], r0, r1, r2, r3;
                ldsm4(r0, r1, r2, r3, st + 10240 + ro);
                wh[0][0] = r0; wh[0][1] = r1; wh[1][0] = r2; wh[1][1] = r3;
                ldsm4(r0, r1, r2, r3, st + 15360 + ro);
                wl[0][0] = r0; wl[0][1] = r1; wl[1][0] = r2; wl[1][1] = r3;
#pragma unroll
                for (int mi = 0; mi < 4; mi++) {
                    mma16816(c[mi][2*j2],   ah[mi], wh[0]);
                    mma16816(c[mi][2*j2],   ah[mi], wl[0]);
                    mma16816(c[mi][2*j2],   al[mi], wh[0]);
                    mma16816(c[mi][2*j2+1], ah[mi], wh[1]);
                    mma16816(c[mi][2*j2+1], ah[mi], wl[1]);
                    mma16816(c[mi][2*j2+1], al[mi], wh[1]);
                }
            }
        }
        __syncthreads();
    }

#pragma unroll
    for (int mi = 0; mi < 4; mi++) {
#pragma unroll
        for (int ni = 0; ni < 8; ni++) {
            const int col = n0 + wn0 + ni * 8 + (lane & 3) * 2;
            float b0 = 0.f, b1 = 0.f;
            if (p.bias) { b0 = p.bias[col]; b1 = p.bias[col + 1]; }
#pragma unroll
            for (int h = 0; h < 2; h++) {
                const int r = m0 + wm0 + mi * 16 + (lane >> 2) + h * 8;
                float v0 = c[mi][ni][h * 2] + b0, v1 = c[mi][ni][h * 2 + 1] + b1;
                if (p.Cf) *(float2*)&p.Cf[(long)r * p.ldc + col] = make_float2(v0, v1);
                if (p.Chi) {
                    __nv_bfloat16 h0 = __float2bfloat16(v0), h1 = __float2bfloat16(v1);
                    __nv_bfloat162 hh; hh.x = h0; hh.y = h1;
                    *(__nv_bfloat162*)&p.Chi[(long)r * p.ldc + col] = hh;
                    __nv_bfloat162 ll;
                    ll.x = __float2bfloat16(v0 - __bfloat162float(h0));
                    ll.y = __float2bfloat16(v1 - __bfloat162float(h1));
                    *(__nv_bfloat162*)&p.Clo[(long)r * p.ldc + col] = ll;
                }
            }
        }
    }
}

// ===================== small kernels =====================
struct Segs {
    const float4* s[9];
    uint2 *h[9], *l[9];
    long off[10];
};

__global__ void k_splitall(Segs sg)
{
    long i = (long)blockIdx.x * 256 + threadIdx.x;
    if (i >= sg.off[9]) return;
    int seg = 0;
    while (i >= sg.off[seg + 1]) seg++;
    const long j = i - sg.off[seg];
    const float4 v = sg.s[seg][j];
    const float vv[4] = {v.x, v.y, v.z, v.w};
    __nv_bfloat16 h[4], l[4];
#pragma unroll
    for (int q = 0; q < 4; q++) {
        h[q] = __float2bfloat16(vv[q]);
        l[q] = __float2bfloat16(vv[q] - __bfloat162float(h[q]));
    }
    sg.h[seg][j] = *(uint2*)h;
    sg.l[seg][j] = *(uint2*)l;
}

__global__ void k_inith(const float* hidden)
{
    long idx = (long)blockIdx.x * 256 + threadIdx.x;   // 0 .. 524287
    float v = hidden[idx];
    g_hf[idx] = v;
    int l = (int)(idx >> 18); long rem = idx & 262143;
    int b = (int)(rem >> 10), j = (int)(rem & 1023);
    __nv_bfloat16 h = __float2bfloat16(v);
    __nv_bfloat16 lo = __float2bfloat16(v - __bfloat162float(h));
    g_ah[(long)l*524288 + b*2048 + 1024 + j] = h;
    g_al[(long)l*524288 + b*2048 + 1024 + j] = lo;
}

// fused logits(h-part, fp32) + softmax + wenc + split.  grid 128, 2 batch rows per CTA.
__global__ void __launch_bounds__(256) k_attn2(
    const float* __restrict__ aW, const float* __restrict__ enc,
    float* __restrict__ out_attn, int t)
{
    const int tid = threadIdx.x, lane = tid & 31, w = tid >> 5;
    const int b0 = blockIdx.x * 2;
    __shared__ float sh1[2][1024];
    __shared__ float slog[2][NS];
    __shared__ float saw[2][NS];

    for (int i = tid; i < 2048; i += 256)
        sh1[i >> 10][i & 1023] = g_hf[262144 + (long)(b0 + (i >> 10)) * 1024 + (i & 1023)];
    __syncthreads();

    for (int s = w; s < NS; s += 8) {
        const float4* wr = reinterpret_cast<const float4*>(aW + (long)s * 2048 + 1024);
        float a0 = 0.f, a1 = 0.f;
#pragma unroll
        for (int i = 0; i < 8; i++) {
            const int j = lane + 32 * i;
            const float4 wv = wr[j];
            const float4 hA = *reinterpret_cast<const float4*>(&sh1[0][j * 4]);
            const float4 hB = *reinterpret_cast<const float4*>(&sh1[1][j * 4]);
            a0 += wv.x*hA.x + wv.y*hA.y + wv.z*hA.z + wv.w*hA.w;
            a1 += wv.x*hB.x + wv.y*hB.y + wv.z*hB.z + wv.w*hB.w;
        }
#pragma unroll
        for (int o = 16; o; o >>= 1) {
            a0 += __shfl_xor_sync(0xffffffffu, a0, o);
            a1 += __shfl_xor_sync(0xffffffffu, a1, o);
        }
        if (lane == 0) {
            slog[0][s] = a0 + g_lx[((long)b0*NT + t)*NS + s];
            slog[1][s] = a1 + g_lx[((long)(b0+1)*NT + t)*NS + s];
        }
    }
    __syncthreads();

    if (w < 2) {
        float v[3];
#pragma unroll
        for (int u = 0; u < 3; u++) v[u] = slog[w][u*32 + lane];
        float mx = fmaxf(v[0], fmaxf(v[1], v[2]));
#pragma unroll
        for (int o = 16; o; o >>= 1) mx = fmaxf(mx, __shfl_xor_sync(0xffffffffu, mx, o));
        float e[3], sum = 0.f;
#pragma unroll
        for (int u = 0; u < 3; u++) { e[u] = expf(v[u] - mx); sum += e[u]; }
#pragma unroll
        for (int o = 16; o; o >>= 1) sum += __shfl_xor_sync(0xffffffffu, sum, o);
        const float inv = 1.0f / sum;
#pragma unroll
        for (int u = 0; u < 3; u++) {
            const int s = u*32 + lane;
            const float wg = e[u] * inv;
            saw[w][s] = wg;
            out_attn[((long)(b0 + w)*NT + t)*NS + s] = wg;
        }
    }
    __syncthreads();

    const int hb = tid >> 7, tl = tid & 127;
    const int b = b0 + hb;
    float4 acc0 = make_float4(0.f,0.f,0.f,0.f), acc1 = acc0;
    const float4* erow = reinterpret_cast<const float4*>(enc + (long)b * NS * NH);
#pragma unroll 4
    for (int s = 0; s < NS; s++) {
        const float wg = saw[hb][s];
        const float4 q0 = erow[s*256 + tl];
        const float4 q1 = erow[s*256 + tl + 128];
        acc0.x += wg*q0.x; acc0.y += wg*q0.y; acc0.z += wg*q0.z; acc0.w += wg*q0.w;
        acc1.x += wg*q1.x; acc1.y += wg*q1.y; acc1.z += wg*q1.z; acc1.w += wg*q1.w;
    }
    const float4 av[2] = {acc0, acc1};
#pragma unroll
    for (int c = 0; c < 2; c++) {
        const float vv[4] = {av[c].x, av[c].y, av[c].z, av[c].w};
        __nv_bfloat16 h[4], l[4];
#pragma unroll
        for (int i = 0; i < 4; i++) {
            h[i] = __float2bfloat16(vv[i]);
            l[i] = __float2bfloat16(vv[i] - __bfloat162float(h[i]));
        }
        const int base = b*1024 + (tl + c*128)*4;
        *(uint2*)&g_weh[base] = *(uint2*)h;
        *(uint2*)&g_wel[base] = *(uint2*)l;
    }
}

// reduce 2 comb split-K partials + combx, relu, split -> a0[:,0:1024]
__global__ void k_combred(const float* __restrict__ addsrc)
{
    const int idx = blockIdx.x * 256 + threadIdx.x;
    const int b = idx >> 10, j = idx & 1023;
    float v = g_g[idx] + g_g[262144 + idx] + addsrc[(long)b * 36864 + j];
    v = fmaxf(v, 0.0f);
    __nv_bfloat16 h = __float2bfloat16(v);
    g_ah[b*2048 + j] = h;
    g_al[b*2048 + j] = __float2bfloat16(v - __bfloat162float(h));
}

// gate: gi = slots 0+1 (splitK), gh = single slot pointer
__global__ void k_gate(const float* __restrict__ ghp,
                       const float* __restrict__ bi, const float* __restrict__ bh,
                       float* __restrict__ hf,
                       __nv_bfloat16* d1h, __nv_bfloat16* d1l,
                       __nv_bfloat16* d2h, __nv_bfloat16* d2l,
                       __nv_bfloat16* d3h, __nv_bfloat16* d3l, long d3off)
{
    const int idx = blockIdx.x * 256 + threadIdx.x;
    const int b = idx >> 10, j = idx & 1023;
    const long o0 = (long)b * N3;
    const float* g0 = g_g + o0;
    const float* g1 = g_g + 786432 + o0;
    const float* gh = ghp + o0;
    const float ir = g0[j]      + g1[j]      + bi[j],      hr = gh[j]      + bh[j];
    const float iz = g0[j+1024] + g1[j+1024] + bi[j+1024], hz = gh[j+1024] + bh[j+1024];
    const float in_ = g0[j+2048] + g1[j+2048] + bi[j+2048], hn = gh[j+2048] + bh[j+2048];
    const float r = 1.0f / (1.0f + expf(-(ir + hr)));
    const float z = 1.0f / (1.0f + expf(-(iz + hz)));
    const float n = tanhf(in_ + r * hn);
    const float h = (1.0f - z) * n + z * hf[idx];
    hf[idx] = h;
    __nv_bfloat16 hh = __float2bfloat16(h);
    __nv_bfloat16 hl = __float2bfloat16(h - __bfloat162float(hh));
    const long o = (long)b*2048 + j;
    d1h[o] = hh; d1l[o] = hl;
    if (d2h) { d2h[o] = hh; d2l[o] = hl; }
    if (d3h) { const long o3 = (long)b*36864 + d3off + j; d3h[o3] = hh; d3l[o3] = hl; }
}

__global__ void k_copy(float* __restrict__ dst, const float* __restrict__ src)
{
    const long i = (long)blockIdx.x * 256 + threadIdx.x;
    dst[i] = src[i];
}

// ===================== launch =====================
extern "C" void kernel_launch(void* const* d_in, const int* in_sizes, int n_in,
                              void* d_out, int out_size)
{
    const float* target = (const float*)d_in[0];
    const float* hidden = (const float*)d_in[1];
    const float* enc    = (const float*)d_in[2];
    const float* aW     = (const float*)d_in[3];
    const float* ab     = (const float*)d_in[4];
    const float* cW     = (const float*)d_in[5];
    const float* cb     = (const float*)d_in[6];
    const float* Wih    = (const float*)d_in[7];
    const float* Whh    = (const float*)d_in[8];
    const float* bih    = (const float*)d_in[9];
    const float* bhh    = (const float*)d_in[10];
    const float* o1W    = (const float*)d_in[11];
    const float* o1b    = (const float*)d_in[12];
    const float* o2W    = (const float*)d_in[13];
    const float* o2b    = (const float*)d_in[14];

    float* out_y    = (float*)d_out;
    float* out_h    = out_y + (long)NB*NT*ND;
    float* out_attn = out_h + (long)2*NB*NH;

    static cudaStream_t sB = nullptr;
    static cudaEvent_t evI, evH0, evH1, evB0, evB1;
    if (!sB) {
        cudaStreamCreateWithFlags(&sB, cudaStreamNonBlocking);
        cudaEventCreateWithFlags(&evI,  cudaEventDisableTiming);
        cudaEventCreateWithFlags(&evH0, cudaEventDisableTiming);
        cudaEventCreateWithFlags(&evH1, cudaEventDisableTiming);
        cudaEventCreateWithFlags(&evB0, cudaEventDisableTiming);
        cudaEventCreateWithFlags(&evB1, cudaEventDisableTiming);
    }

    cudaFuncSetAttribute(gemm_big, cudaFuncAttributeMaxDynamicSharedMemorySize, BIGSM);

    __nv_bfloat16 *th, *tl, *aWh, *aWl, *cWh, *cWl, *Wgh, *Wgl, *o1h, *o1l, *o2h, *o2l;
    __nv_bfloat16 *tmph, *tmpl, *h1h, *h1l, *weh, *wel, *ah, *al;
    float *combx, *lx, *gg, *hf;
    cudaGetSymbolAddress((void**)&th, g_th);     cudaGetSymbolAddress((void**)&tl, g_tl);
    cudaGetSymbolAddress((void**)&aWh, g_aWh);   cudaGetSymbolAddress((void**)&aWl, g_aWl);
    cudaGetSymbolAddress((void**)&cWh, g_cWh);   cudaGetSymbolAddress((void**)&cWl, g_cWl);
    cudaGetSymbolAddress((void**)&Wgh, g_Wgh);   cudaGetSymbolAddress((void**)&Wgl, g_Wgl);
    cudaGetSymbolAddress((void**)&o1h, g_o1h);   cudaGetSymbolAddress((void**)&o1l, g_o1l);
    cudaGetSymbolAddress((void**)&o2h, g_o2h);   cudaGetSymbolAddress((void**)&o2l, g_o2l);
    cudaGetSymbolAddress((void**)&tmph, g_tmph); cudaGetSymbolAddress((void**)&tmpl, g_tmpl);
    cudaGetSymbolAddress((void**)&h1h, g_h1h);   cudaGetSymbolAddress((void**)&h1l, g_h1l);
    cudaGetSymbolAddress((void**)&weh, g_weh);   cudaGetSymbolAddress((void**)&wel, g_wel);
    cudaGetSymbolAddress((void**)&ah, g_ah);     cudaGetSymbolAddress((void**)&al, g_al);
    cudaGetSymbolAddress((void**)&combx, g_combx);
    cudaGetSymbolAddress((void**)&lx, g_lx);
    cudaGetSymbolAddress((void**)&gg, g_g);
    cudaGetSymbolAddress((void**)&hf, g_hf);

    __nv_bfloat16 *a0h = ah, *a0l = al, *a1h = ah + 524288, *a1l = al + 524288;

    // ---- pre ----
    {
        Segs sg;
        const float* srcs[9] = {target, aW, cW, Wih, Whh, Wih + 3145728, Whh + 3145728, o1W, o2W};
        __nv_bfloat16* dh[9] = {th, aWh, cWh, Wgh, Wgh + 3145728, Wgh + 2L*3145728, Wgh + 3L*3145728, o1h, o2h};
        __nv_bfloat16* dl[9] = {tl, aWl, cWl, Wgl, Wgl + 3145728, Wgl + 2L*3145728, Wgl + 3L*3145728, o1l, o2l};
        const long cnt[9] = {2359296, 49152, 524288, 786432, 786432, 786432, 786432, 262144, 262144};
        long acc = 0;
        for (int i = 0; i < 9; i++) {
            sg.s[i] = (const float4*)srcs[i]; sg.h[i] = (uint2*)dh[i]; sg.l[i] = (uint2*)dl[i];
            sg.off[i] = acc; acc += cnt[i];
        }
        sg.off[9] = acc;
        k_splitall<<<(unsigned)((acc + 255) / 256), 256>>>(sg);
    }
    k_inith<<<2048, 256>>>(hidden);
    {   // lx = target @ aW[:, :D].T + ab
        GP p = {}; p.Ah = th; p.Al = tl; p.lda = 1024; p.Wh = aWh; p.Wl = aWl; p.ldw = 2048;
        p.Cf = lx; p.ldc = 96; p.bias = ab; p.K = 1024;
        gemm_bf16<64,32,32,16><<<dim3(3,144,1), 128>>>(p);
    }
    {   // combx = target @ cW[:, :D].T + cb
        GB q = {}; q.Ah = th; q.Al = tl; q.lda = 1024; q.Wh = cWh; q.Wl = cWl; q.ldw = 2048;
        q.Cf = combx; q.ldc = 1024; q.bias = cb; q.K = 1024;
        gemm_big<<<dim3(8,72,1), 128, BIGSM>>>(q);
    }
    // initial gh0(0), gh1(0) on stream B
    cudaEventRecord(evI, 0);
    cudaStreamWaitEvent(sB, evI, 0);
    {   // gh0 = h0 @ Whh0.T -> slot 2
        GP p = {}; p.Ah = a0h + 1024; p.Al = a0l + 1024; p.lda = 2048;
        p.Wh = Wgh + 3145728; p.Wl = Wgl + 3145728; p.ldw = 1024;
        p.Cf = gg + 2L*786432; p.ldc = 3072; p.K = 1024;
        gemm_bf16<64,64,32,32><<<dim3(48,4,1), 128, 0, sB>>>(p);
    }
    cudaEventRecord(evB0, sB);
    {   // gh1 = h1 @ Whh1.T -> slot 3
        GP p = {}; p.Ah = a1h + 1024; p.Al = a1l + 1024; p.lda = 2048;
        p.Wh = Wgh + 3L*3145728; p.Wl = Wgl + 3L*3145728; p.ldw = 1024;
        p.Cf = gg + 3L*786432; p.ldc = 3072; p.K = 1024;
        gemm_bf16<64,64,32,32><<<dim3(48,4,1), 128, 0, sB>>>(p);
    }
    cudaEventRecord(evB1, sB);

    // ---- recurrent loop ----
    for (int t = 0; t < NT; t++) {
        k_attn2<<<128, 256>>>(aW, enc, out_attn, t);
        {   // comb: wenc @ cW[:, D:].T  splitK2 -> slots 0,1 (1024-wide)
            GP p = {}; p.Ah = weh; p.Al = wel; p.lda = 1024;
            p.Wh = cWh + 1024; p.Wl = cWl + 1024; p.ldw = 2048;
            p.Cf = gg; p.scz = 262144; p.ldc = 1024; p.K = 512; p.kz = 512;
            gemm_bf16<64,64,32,32><<<dim3(16,4,2), 128>>>(p);
        }
        k_combred<<<1024, 256>>>(combx + (long)t * 1024);
        {   // gi0 = xc @ Wih0.T  splitK2 -> slots 0,1
            GP p = {}; p.Ah = a0h; p.Al = a0l; p.lda = 2048;
            p.Wh = Wgh; p.Wl = Wgl; p.ldw = 1024;
            p.Cf = gg; p.scz = 786432; p.ldc = 3072; p.K = 512; p.kz = 512;
            gemm_bf16<64,64,32,32><<<dim3(48,4,2), 128>>>(p);
        }
        cudaStreamWaitEvent(0, evB0, 0);
        k_gate<<<1024, 256>>>(gg + 2L*786432, bih, bhh, hf,
                              a1h, a1l, a0h + 1024, a0l + 1024, nullptr, nullptr, 0);
        if (t + 1 < NT) {
            cudaEventRecord(evH0, 0);
            cudaStreamWaitEvent(sB, evH0, 0);
            GP p = {}; p.Ah = a0h + 1024; p.Al = a0l + 1024; p.lda = 2048;
            p.Wh = Wgh + 3145728; p.Wl = Wgl + 3145728; p.ldw = 1024;
            p.Cf = gg + 2L*786432; p.ldc = 3072; p.K = 1024;
            gemm_bf16<64,64,32,32><<<dim3(48,4,1), 128, 0, sB>>>(p);
            cudaEventRecord(evB0, sB);
        }
        {   // gi1 = h0' @ Wih1.T  splitK2 -> slots 0,1
            GP p = {}; p.Ah = a1h; p.Al = a1l; p.lda = 2048;
            p.Wh = Wgh + 2L*3145728; p.Wl = Wgl + 2L*3145728; p.ldw = 1024;
            p.Cf = gg; p.scz = 786432; p.ldc = 3072; p.K = 512; p.kz = 512;
            gemm_bf16<64,64,32,32><<<dim3(48,4,2), 128>>>(p);
        }
        cudaStreamWaitEvent(0, evB1, 0);
        k_gate<<<1024, 256>>>(gg + 3L*786432, bih + 3072, bhh + 3072, hf + 262144,
                              a1h + 1024, a1l + 1024, nullptr, nullptr, h1h, h1l, (long)t*1024);
        if (t + 1 < NT) {
            cudaEventRecord(evH1, 0);
            cudaStreamWaitEvent(sB, evH1, 0);
            GP p = {}; p.Ah = a1h + 1024; p.Al = a1l + 1024; p.lda = 2048;
            p.Wh = Wgh + 3L*3145728; p.Wl = Wgl + 3L*3145728; p.ldw = 1024;
            p.Cf = gg + 3L*786432; p.ldc = 3072; p.K = 1024;
            gemm_bf16<64,64,32,32><<<dim3(48,4,1), 128, 0, sB>>>(p);
            cudaEventRecord(evB1, sB);
        }
    }

    // ---- deferred output head ----
    {
        GB q = {}; q.Ah = h1h; q.Al = h1l; q.lda = 1024; q.Wh = o1h; q.Wl = o1l; q.ldw = 1024;
        q.Chi = tmph; q.Clo = tmpl; q.ldc = 1024; q.bias = o1b; q.K = 1024;
        gemm_big<<<dim3(8,72,1), 128, BIGSM>>>(q);
    }
    {
        GB q = {}; q.Ah = tmph; q.Al = tmpl; q.lda = 1024; q.Wh = o2h; q.Wl = o2l; q.ldw = 1024;
        q.Cf = out_y; q.ldc = 1024; q.bias = o2b; q.K = 1024;
        gemm_big<<<dim3(8,72,1), 128, BIGSM>>>(q);
    }
    k_copy<<<2048, 256>>>(out_h, hf);
}